// round 1
// baseline (speedup 1.0000x reference)
#include <cuda_runtime.h>
#include <math.h>

// Problem constants
#define Bb   4
#define Ss   1024
#define Dd   1024
#define Hh   16
#define DKk  64
#define Rr   257          // 2*MAX_REL + 1
#define BHh  64           // B*H
#define Mm   4096         // B*S
#define BHS  65536        // B*H*S
#define SCALEF 0.125f     // 1/sqrt(64)

// ---------------- scratch (device globals; no runtime allocation) ----------------
__device__ float g_Q[BHS * DKk];          // [B,H,S,DK]  16 MB
__device__ float g_K[BHS * DKk];
__device__ float g_V[BHS * DKk];
__device__ float g_ctx[BHS * DKk];
__device__ float g_Qrel[BHS * Rr];        // [B,H,S,257] 67 MB
__device__ float g_arel[BHS * Rr];        // bucketed attention
__device__ float g_attn[67108864];        // [B,H,S,S]  256 MB (scores -> probs in place)

// =================================================================================
// Kernel 1: QKV projection.  C[m,n] = sum_k X[m,k] * W[n,k] + bias[n]
// output written head-split: out[((b*H+h)*S+s)*DK+dk], n = h*64+dk, m = b*S+s
// grid (N/64=16, M/64=64), 256 threads
// =================================================================================
__global__ void proj_kernel(const float* __restrict__ X, const float* __restrict__ W,
                            const float* __restrict__ bias, float* __restrict__ out)
{
    __shared__ float As[64][17];
    __shared__ float Ws[64][17];
    int n0 = blockIdx.x * 64, m0 = blockIdx.y * 64;
    int tid = threadIdx.x, tx = tid & 15, ty = tid >> 4;
    float acc[4][4] = {};
    for (int k0 = 0; k0 < Dd; k0 += 16) {
        #pragma unroll
        for (int i = 0; i < 4; i++) {
            As[ty + 16 * i][tx] = X[(m0 + ty + 16 * i) * Dd + k0 + tx];
            Ws[ty + 16 * i][tx] = W[(n0 + ty + 16 * i) * Dd + k0 + tx];
        }
        __syncthreads();
        #pragma unroll
        for (int kk = 0; kk < 16; kk++) {
            float a[4], b[4];
            #pragma unroll
            for (int i = 0; i < 4; i++) a[i] = As[ty + 16 * i][kk];
            #pragma unroll
            for (int j = 0; j < 4; j++) b[j] = Ws[tx + 16 * j][kk];
            #pragma unroll
            for (int i = 0; i < 4; i++)
                #pragma unroll
                for (int j = 0; j < 4; j++) acc[i][j] += a[i] * b[j];
        }
        __syncthreads();
    }
    #pragma unroll
    for (int i = 0; i < 4; i++) {
        int m = m0 + ty + 16 * i;
        int b = m >> 10, s = m & 1023;
        #pragma unroll
        for (int j = 0; j < 4; j++) {
            int n = n0 + tx + 16 * j;
            int h = n >> 6, dk = n & 63;
            out[((b * Hh + h) * Ss + s) * DKk + dk] = acc[i][j] + bias[n];
        }
    }
}

// =================================================================================
// Kernel 2: Qrel[m, p] = sum_d g_Q[m, d] * rel_k[p, d]   (m over B*H*S, p < 257)
// grid (ceil(257/64)=5, 65536/64=1024), 256 threads, full K=64 in smem
// =================================================================================
__global__ void qrel_kernel(const float* __restrict__ relk)
{
    __shared__ float As[64][65];
    __shared__ float Bs[64][65];
    int n0 = blockIdx.x * 64, m0 = blockIdx.y * 64;
    int tid = threadIdx.x, tx = tid & 15, ty = tid >> 4;
    for (int i = tid; i < 64 * 64; i += 256) {
        int r = i >> 6, c = i & 63;
        As[r][c] = g_Q[(m0 + r) * DKk + c];
        Bs[r][c] = (n0 + r < Rr) ? relk[(n0 + r) * DKk + c] : 0.f;
    }
    __syncthreads();
    float acc[4][4] = {};
    #pragma unroll
    for (int kk = 0; kk < 64; kk++) {
        float a[4], b[4];
        #pragma unroll
        for (int i = 0; i < 4; i++) a[i] = As[ty + 16 * i][kk];
        #pragma unroll
        for (int j = 0; j < 4; j++) b[j] = Bs[tx + 16 * j][kk];
        #pragma unroll
        for (int i = 0; i < 4; i++)
            #pragma unroll
            for (int j = 0; j < 4; j++) acc[i][j] += a[i] * b[j];
    }
    #pragma unroll
    for (int i = 0; i < 4; i++)
        #pragma unroll
        for (int j = 0; j < 4; j++) {
            int n = n0 + tx + 16 * j;
            if (n < Rr) g_Qrel[(m0 + ty + 16 * i) * Rr + n] = acc[i][j];
        }
}

// =================================================================================
// Kernel 3: scores[z,l,r] = SCALE * (Q[z,l,:].K[z,r,:]) + Qrel[z,l, clip(r-l)+128]
//           (+ mask)  -> g_attn
// grid (S/64=16, S/64=16, B*H=64), 256 threads
// =================================================================================
__global__ void scores_kernel(const int* __restrict__ mask)
{
    __shared__ float Qs[64][65];
    __shared__ float Ks[64][65];
    int z = blockIdx.z;
    int r0 = blockIdx.x * 64, l0 = blockIdx.y * 64;
    const float* Qb = g_Q + (size_t)z * Ss * DKk;
    const float* Kb = g_K + (size_t)z * Ss * DKk;
    int tid = threadIdx.x, tx = tid & 15, ty = tid >> 4;
    for (int i = tid; i < 64 * 64; i += 256) {
        int r = i >> 6, c = i & 63;
        Qs[r][c] = Qb[(l0 + r) * DKk + c];
        Ks[r][c] = Kb[(r0 + r) * DKk + c];
    }
    __syncthreads();
    float acc[4][4] = {};
    #pragma unroll
    for (int kk = 0; kk < 64; kk++) {
        float a[4], b[4];
        #pragma unroll
        for (int i = 0; i < 4; i++) a[i] = Qs[ty + 16 * i][kk];
        #pragma unroll
        for (int j = 0; j < 4; j++) b[j] = Ks[tx + 16 * j][kk];
        #pragma unroll
        for (int i = 0; i < 4; i++)
            #pragma unroll
            for (int j = 0; j < 4; j++) acc[i][j] += a[i] * b[j];
    }
    int bidx = z >> 4;  // z / H
    #pragma unroll
    for (int i = 0; i < 4; i++) {
        int l = l0 + ty + 16 * i;
        const float* qr = &g_Qrel[(size_t)(z * Ss + l) * Rr];
        #pragma unroll
        for (int j = 0; j < 4; j++) {
            int r = r0 + tx + 16 * j;
            float sc = acc[i][j] * SCALEF;
            int rel = r - l;
            rel = rel < -128 ? -128 : (rel > 128 ? 128 : rel);
            sc += qr[rel + 128];
            if (mask[bidx * Ss + r] == 0) sc = -1000000000.0f;
            g_attn[(size_t)(z * Ss + l) * Ss + r] = sc;
        }
    }
}

// =================================================================================
// Kernel 4: softmax over each row of g_attn (in place) + relative-position buckets
// grid (BHS), 256 threads.  attn_rel[row, p]:
//   p in [1,255]: single element probs[l + p - 128] (if in range)
//   p = 0:   sum_{r <= l-128} probs[r];   p = 256: sum_{r >= l+128} probs[r]
// =================================================================================
__global__ void softmax_kernel()
{
    __shared__ float sm[Ss];
    __shared__ float red[256];
    int row = blockIdx.x;
    int l = row & (Ss - 1);
    float* prow = &g_attn[(size_t)row * Ss];
    int tid = threadIdx.x;

    float lmax = -INFINITY;
    for (int r = tid; r < Ss; r += 256) { float v = prow[r]; sm[r] = v; lmax = fmaxf(lmax, v); }
    red[tid] = lmax; __syncthreads();
    for (int s = 128; s > 0; s >>= 1) { if (tid < s) red[tid] = fmaxf(red[tid], red[tid + s]); __syncthreads(); }
    float mx = red[0];
    __syncthreads();

    float lsum = 0.f;
    for (int r = tid; r < Ss; r += 256) { float e = expf(sm[r] - mx); sm[r] = e; lsum += e; }
    red[tid] = lsum; __syncthreads();
    for (int s = 128; s > 0; s >>= 1) { if (tid < s) red[tid] += red[tid + s]; __syncthreads(); }
    float inv = 1.f / red[0];
    __syncthreads();

    for (int r = tid; r < Ss; r += 256) { float p = sm[r] * inv; sm[r] = p; prow[r] = p; }
    __syncthreads();

    float* arow = &g_arel[(size_t)row * Rr];
    // interior buckets (p=0 and p=256 rewritten below by tid 0 - same-thread ordering)
    for (int p = tid; p < Rr; p += 256) {
        float v = 0.f;
        if (p >= 1 && p <= 255) {
            int r = l + p - 128;
            if (r >= 0 && r < Ss) v = sm[r];
        }
        arow[p] = v;
    }
    // bucket 0: prefix sum over r in [0, l-128]
    float s0 = 0.f;
    for (int r = tid; r <= l - 128; r += 256) s0 += sm[r];
    red[tid] = s0; __syncthreads();
    for (int s = 128; s > 0; s >>= 1) { if (tid < s) red[tid] += red[tid + s]; __syncthreads(); }
    if (tid == 0) arow[0] = red[0];
    __syncthreads();
    // bucket 256: suffix sum over r in [l+128, S)
    float s1 = 0.f;
    for (int r = l + 128 + tid; r < Ss; r += 256) s1 += sm[r];
    red[tid] = s1; __syncthreads();
    for (int s = 128; s > 0; s >>= 1) { if (tid < s) red[tid] += red[tid + s]; __syncthreads(); }
    if (tid == 0) arow[256] = red[0];
}

// =================================================================================
// Kernel 5: context[z,l,d] = sum_r attn[z,l,r]*V[z,r,d] + sum_p arel[z,l,p]*rel_v[p,d]
// grid (S/64=16, B*H=64), 256 threads. B operand is K-major-in-rows (V[r][d]).
// =================================================================================
__global__ void context_kernel(const float* __restrict__ relv)
{
    __shared__ float As[64][65];  // [l][k]
    __shared__ float Bs[64][65];  // [k][d]
    int z = blockIdx.y;
    int l0 = blockIdx.x * 64;
    int tid = threadIdx.x, tx = tid & 15, ty = tid >> 4;
    const float* Vb = g_V + (size_t)z * Ss * DKk;
    float acc[4][4] = {};

    for (int r0 = 0; r0 < Ss; r0 += 64) {
        for (int i = tid; i < 64 * 64; i += 256) {
            int r = i >> 6, c = i & 63;
            As[r][c] = g_attn[(size_t)(z * Ss + l0 + r) * Ss + r0 + c];
            Bs[r][c] = Vb[(r0 + r) * DKk + c];
        }
        __syncthreads();
        #pragma unroll
        for (int kk = 0; kk < 64; kk++) {
            float a[4], b[4];
            #pragma unroll
            for (int i = 0; i < 4; i++) a[i] = As[ty + 16 * i][kk];
            #pragma unroll
            for (int j = 0; j < 4; j++) b[j] = Bs[kk][tx + 16 * j];
            #pragma unroll
            for (int i = 0; i < 4; i++)
                #pragma unroll
                for (int j = 0; j < 4; j++) acc[i][j] += a[i] * b[j];
        }
        __syncthreads();
    }
    // relative-value part: K = 257 in chunks of 64
    for (int p0 = 0; p0 < Rr; p0 += 64) {
        int pc = Rr - p0; if (pc > 64) pc = 64;
        for (int i = tid; i < 64 * 64; i += 256) {
            int r = i >> 6, c = i & 63;
            As[r][c] = (c < pc) ? g_arel[(size_t)(z * Ss + l0 + r) * Rr + p0 + c] : 0.f;
            Bs[r][c] = (r < pc) ? relv[(p0 + r) * DKk + c] : 0.f;
        }
        __syncthreads();
        #pragma unroll
        for (int kk = 0; kk < 64; kk++) {
            float a[4], b[4];
            #pragma unroll
            for (int i = 0; i < 4; i++) a[i] = As[ty + 16 * i][kk];
            #pragma unroll
            for (int j = 0; j < 4; j++) b[j] = Bs[kk][tx + 16 * j];
            #pragma unroll
            for (int i = 0; i < 4; i++)
                #pragma unroll
                for (int j = 0; j < 4; j++) acc[i][j] += a[i] * b[j];
        }
        __syncthreads();
    }
    #pragma unroll
    for (int i = 0; i < 4; i++)
        #pragma unroll
        for (int j = 0; j < 4; j++)
            g_ctx[(size_t)(z * Ss + l0 + ty + 16 * i) * DKk + tx + 16 * j] = acc[i][j];
}

// =================================================================================
// Kernel 6: out[m,n] = sum_k ctx_perm[m,k] * w_o[n,k] + b_o[n]
// ctx_perm(m,k): b=m>>10, s=m&1023, h=k>>6, dk=k&63 -> g_ctx[((b*H+h)*S+s)*64+dk]
// grid (16, 64), 256 threads
// =================================================================================
__global__ void outproj_kernel(const float* __restrict__ Wo, const float* __restrict__ bo,
                               float* __restrict__ out)
{
    __shared__ float As[64][17];
    __shared__ float Ws[64][17];
    int n0 = blockIdx.x * 64, m0 = blockIdx.y * 64;
    int tid = threadIdx.x, tx = tid & 15, ty = tid >> 4;
    float acc[4][4] = {};
    for (int k0 = 0; k0 < Dd; k0 += 16) {
        int h = (k0 + 0) >> 6;          // k0 is 16-aligned; whole chunk within one head
        int dk0 = k0 & 63;
        #pragma unroll
        for (int i = 0; i < 4; i++) {
            int m = m0 + ty + 16 * i;
            int b = m >> 10, s = m & 1023;
            As[ty + 16 * i][tx] = g_ctx[((b * Hh + h) * Ss + s) * DKk + dk0 + tx];
            Ws[ty + 16 * i][tx] = Wo[(n0 + ty + 16 * i) * Dd + k0 + tx];
        }
        __syncthreads();
        #pragma unroll
        for (int kk = 0; kk < 16; kk++) {
            float a[4], b[4];
            #pragma unroll
            for (int i = 0; i < 4; i++) a[i] = As[ty + 16 * i][kk];
            #pragma unroll
            for (int j = 0; j < 4; j++) b[j] = Ws[tx + 16 * j][kk];
            #pragma unroll
            for (int i = 0; i < 4; i++)
                #pragma unroll
                for (int j = 0; j < 4; j++) acc[i][j] += a[i] * b[j];
        }
        __syncthreads();
    }
    #pragma unroll
    for (int i = 0; i < 4; i++) {
        int m = m0 + ty + 16 * i;
        #pragma unroll
        for (int j = 0; j < 4; j++) {
            int n = n0 + tx + 16 * j;
            out[m * Dd + n] = acc[i][j] + bo[n];
        }
    }
}

// helper to fetch device-symbol addresses once per launch (cheap, capture-safe:
// kernels reference globals directly; only Q/K/V targets need a pointer)
extern "C" void kernel_launch(void* const* d_in, const int* in_sizes, int n_in,
                              void* d_out, int out_size)
{
    const float* query = (const float*)d_in[0];
    const float* key   = (const float*)d_in[1];
    const float* value = (const float*)d_in[2];
    const int*   mask  = (const int*)  d_in[3];
    const float* w_q   = (const float*)d_in[4];
    const float* b_q   = (const float*)d_in[5];
    const float* w_k   = (const float*)d_in[6];
    const float* b_k   = (const float*)d_in[7];
    const float* w_v   = (const float*)d_in[8];
    const float* b_v   = (const float*)d_in[9];
    const float* w_o   = (const float*)d_in[10];
    const float* b_o   = (const float*)d_in[11];
    const float* rel_k = (const float*)d_in[12];
    const float* rel_v = (const float*)d_in[13];
    float* out = (float*)d_out;

    float *pQ, *pK, *pV;
    cudaGetSymbolAddress((void**)&pQ, g_Q);
    cudaGetSymbolAddress((void**)&pK, g_K);
    cudaGetSymbolAddress((void**)&pV, g_V);

    dim3 gProj(Dd / 64, Mm / 64);            // (16, 64)
    proj_kernel<<<gProj, 256>>>(query, w_q, b_q, pQ);
    proj_kernel<<<gProj, 256>>>(key,   w_k, b_k, pK);
    proj_kernel<<<gProj, 256>>>(value, w_v, b_v, pV);

    dim3 gQrel((Rr + 63) / 64, BHS / 64);    // (5, 1024)
    qrel_kernel<<<gQrel, 256>>>(rel_k);

    dim3 gScores(Ss / 64, Ss / 64, BHh);     // (16, 16, 64)
    scores_kernel<<<gScores, 256>>>(mask);

    softmax_kernel<<<BHS, 256>>>();

    dim3 gCtx(Ss / 64, BHh);                 // (16, 64)
    context_kernel<<<gCtx, 256>>>(rel_v);

    dim3 gOut(Dd / 64, Mm / 64);             // (16, 64)
    outproj_kernel<<<gOut, 256>>>(w_o, b_o, out);
}